// round 5
// baseline (speedup 1.0000x reference)
#include <cuda_runtime.h>
#include <mma.h>
#include <cstdint>
#include <cstdio>

using namespace nvcuda;

#define T_LEN 512
#define BATCH 64
#define ISZ   512
#define HSZ   1024
#define HX    1536
#define NC    128      // c-groups == CTAs in sequential kernel
#define RPC   32       // gate rows per c-group (f8,i8,c8,o8)
#define JPC   8        // h columns per c-group

// ---------------- static device scratch (no cudaMalloc allowed) ----------------
__device__ float    g_Wrec[NC * HSZ * RPC];              // [c][k][r] tf32-rounded, 16 MB
__device__ float    g_Wx[NC * ISZ * RPC];                // [c][k][r] tf32-rounded, 8 MB
__device__ float    g_bg[NC * RPC];                      // packed biases
__device__ float    g_Gx[(size_t)T_LEN * NC * BATCH * RPC]; // [t][c][b][r], 512 MB
__device__ float    g_h[2 * BATCH * HSZ];                // double-buffered hidden state
__device__ unsigned g_bar;                               // grid barrier counter

__global__ void reset_kernel() { g_bar = 0u; }

// ---------------- pack: transpose weights into per-c k-major blocks ----------------
__global__ void pack_kernel(const float* __restrict__ Wf, const float* __restrict__ Wi,
                            const float* __restrict__ Wc, const float* __restrict__ Wo,
                            const float* __restrict__ bf, const float* __restrict__ bi,
                            const float* __restrict__ bc, const float* __restrict__ bo)
{
    int idx = blockIdx.x * blockDim.x + threadIdx.x;
    const int N1 = NC * HSZ * RPC;   // 4194304
    const int N2 = NC * ISZ * RPC;   // 2097152
    if (idx < N1) {
        int r = idx & 31; int k = (idx >> 5) & 1023; int c = idx >> 15;
        int gate = r >> 3; int j = c * JPC + (r & 7);
        const float* W = (gate == 0) ? Wf : (gate == 1) ? Wi : (gate == 2) ? Wc : Wo;
        g_Wrec[idx] = wmma::__float_to_tf32(W[(size_t)j * HX + k]);
        (void)k;
    } else if (idx < N1 + N2) {
        int t2 = idx - N1;
        int r = t2 & 31; int k = (t2 >> 5) & 511; int c = t2 >> 14;
        int gate = r >> 3; int j = c * JPC + (r & 7);
        const float* W = (gate == 0) ? Wf : (gate == 1) ? Wi : (gate == 2) ? Wc : Wo;
        g_Wx[t2] = wmma::__float_to_tf32(W[(size_t)j * HX + HSZ + k]);
    } else if (idx < N1 + N2 + NC * RPC) {
        int t3 = idx - N1 - N2;
        int r = t3 & 31; int c = t3 >> 5;
        int gate = r >> 3; int j = c * JPC + (r & 7);
        const float* b = (gate == 0) ? bf : (gate == 1) ? bi : (gate == 2) ? bc : bo;
        g_bg[t3] = b[j];
    }
}

// ---------------- Gx = x @ Wx^T, written as [t][c][b][r] ----------------
#define GX_LDA 132
#define GX_SMEM (2 * 128 * GX_LDA * 4)

__global__ __launch_bounds__(256, 1) void gx_kernel(const float* __restrict__ x)
{
    extern __shared__ float sm[];
    float* As = sm;                   // 128 x 132
    float* Bs = sm + 128 * GX_LDA;    // 128 x 132
    int tid = threadIdx.x;
    int w = tid >> 5;
    int m0 = blockIdx.y * 128;        // 2 timesteps
    int n0 = blockIdx.x * 128;        // 4 c-groups
    int c0 = n0 >> 5;

    wmma::fragment<wmma::accumulator, 16, 16, 8, float> acc[8];
#pragma unroll
    for (int i = 0; i < 8; i++) wmma::fill_fragment(acc[i], 0.f);

    for (int kb = 0; kb < ISZ; kb += 128) {
        // stage A (x), tf32-rounded
#pragma unroll
        for (int it = 0; it < 16; ++it) {
            int p4 = tid + it * 256;
            int row = p4 >> 5, col4 = p4 & 31;
            float4 v = *(const float4*)(x + (size_t)(m0 + row) * ISZ + kb + col4 * 4);
            v.x = wmma::__float_to_tf32(v.x); v.y = wmma::__float_to_tf32(v.y);
            v.z = wmma::__float_to_tf32(v.z); v.w = wmma::__float_to_tf32(v.w);
            *(float4*)(As + row * GX_LDA + col4 * 4) = v;
        }
        // stage B (g_Wx already tf32-rounded); source blocks are contiguous
#pragma unroll
        for (int it = 0; it < 16; ++it) {
            int p4 = tid + it * 256;
            int cl = p4 >> 10; int rem = p4 & 1023;
            int k = rem >> 3; int r4 = rem & 7;
            float4 v = *(const float4*)(g_Wx + ((size_t)(c0 + cl) * ISZ + kb + k) * RPC + r4 * 4);
            *(float4*)(Bs + k * GX_LDA + cl * 32 + r4 * 4) = v;
        }
        __syncthreads();
#pragma unroll 4
        for (int ks = 0; ks < 128; ks += 8) {
            wmma::fragment<wmma::matrix_a, 16, 16, 8, wmma::precision::tf32, wmma::row_major> a;
            wmma::load_matrix_sync(a, As + (w * 16) * GX_LDA + ks, GX_LDA);
#pragma unroll
            for (int nt = 0; nt < 8; ++nt) {
                wmma::fragment<wmma::matrix_b, 16, 16, 8, wmma::precision::tf32, wmma::row_major> b;
                wmma::load_matrix_sync(b, Bs + ks * GX_LDA + nt * 16, GX_LDA);
                wmma::mma_sync(acc[nt], a, b, acc[nt]);
            }
        }
        __syncthreads();
    }
    // epilogue: m-tile of 16 stays inside a single timestep (64 | 16)
    int mg = m0 + w * 16;
    int t = mg >> 6; int b0 = mg & 63;
#pragma unroll
    for (int nt = 0; nt < 8; ++nt) {
        int ng = n0 + nt * 16;
        int c = ng >> 5; int r0 = ng & 31;
        float* dst = g_Gx + ((size_t)(t * NC + c) * BATCH + b0) * RPC + r0;
        wmma::store_matrix_sync(dst, acc[nt], RPC, wmma::mem_row_major);
    }
}

// ---------------- persistent sequential LSTM kernel ----------------
#define SEQ_LDA 132
#define SEQ_SMEM ((HSZ * RPC + 2 * BATCH * SEQ_LDA + BATCH * RPC + BATCH * JPC + RPC) * 4)

__device__ __forceinline__ void grid_barrier(unsigned target)
{
    __syncthreads();
    if (threadIdx.x == 0) {
        __threadfence();
        atomicAdd(&g_bar, 1u);
        while (atomicAdd(&g_bar, 0u) < target) __nanosleep(32);
    }
    __syncthreads();
}

__global__ __launch_bounds__(256, 1) void lstm_seq_kernel(float* __restrict__ out)
{
    extern __shared__ float sm[];
    float* Ws  = sm;                               // [1024][32] Wh slice (tf32) 128 KB
    float* Ahi = Ws + HSZ * RPC;                   // [64][132] h hi
    float* Alo = Ahi + BATCH * SEQ_LDA;            // [64][132] h lo
    float* Gs  = Alo + BATCH * SEQ_LDA;            // [64][32] gate preacts
    float* Cs  = Gs + BATCH * RPC;                 // [64][8] cell state
    float* Bg  = Cs + BATCH * JPC;                 // [32] biases

    int tid = threadIdx.x;
    int w = tid >> 5;
    int cb = blockIdx.x;

    // ---- init ----
    {
        const float4* wsrc = (const float4*)(g_Wrec + (size_t)cb * HSZ * RPC);
        float4* wdst = (float4*)Ws;
        for (int i = tid; i < HSZ * RPC / 4; i += 256) wdst[i] = wsrc[i];
        if (tid < RPC) Bg[tid] = g_bg[cb * RPC + tid];
        for (int i = tid; i < BATCH * JPC; i += 256) {
            Cs[i] = 0.f;
            int b = i >> 3, j = i & 7;
            g_h[b * HSZ + cb * JPC + j] = 0.f;   // h_{-1} in buffer 0
        }
    }
    unsigned target = NC;
    grid_barrier(target);

    int mt = w >> 1, nt = w & 1;                   // 4 m-tiles x 2 n-tiles

    for (int t = 0; t < T_LEN; ++t) {
        const float* hread = g_h + (size_t)(t & 1) * BATCH * HSZ;
        float* hwrite      = g_h + (size_t)((t + 1) & 1) * BATCH * HSZ;

        wmma::fragment<wmma::accumulator, 16, 16, 8, float> acc;
        wmma::fill_fragment(acc, 0.f);

        for (int kb = 0; kb < 8; ++kb) {           // 8 chunks of K=128
            // stage h chunk as tf32 hi/lo (L2 reads, bypass stale L1)
#pragma unroll
            for (int it = 0; it < 8; ++it) {
                int p4 = tid + it * 256;
                int b = p4 >> 5, kk4 = p4 & 31;
                float4 v = __ldcg((const float4*)(hread + b * HSZ + kb * 128 + kk4 * 4));
                float4 hi, lo;
                hi.x = wmma::__float_to_tf32(v.x); lo.x = wmma::__float_to_tf32(v.x - hi.x);
                hi.y = wmma::__float_to_tf32(v.y); lo.y = wmma::__float_to_tf32(v.y - hi.y);
                hi.z = wmma::__float_to_tf32(v.z); lo.z = wmma::__float_to_tf32(v.z - hi.z);
                hi.w = wmma::__float_to_tf32(v.w); lo.w = wmma::__float_to_tf32(v.w - hi.w);
                *(float4*)(Ahi + b * SEQ_LDA + kk4 * 4) = hi;
                *(float4*)(Alo + b * SEQ_LDA + kk4 * 4) = lo;
            }
            __syncthreads();
#pragma unroll 4
            for (int ks = 0; ks < 128; ks += 8) {
                wmma::fragment<wmma::matrix_b, 16, 16, 8, wmma::precision::tf32, wmma::row_major> bmat;
                wmma::load_matrix_sync(bmat, Ws + (kb * 128 + ks) * RPC + nt * 16, RPC);
                wmma::fragment<wmma::matrix_a, 16, 16, 8, wmma::precision::tf32, wmma::row_major> a;
                wmma::load_matrix_sync(a, Ahi + (mt * 16) * SEQ_LDA + ks, SEQ_LDA);
                wmma::mma_sync(acc, a, bmat, acc);
                wmma::load_matrix_sync(a, Alo + (mt * 16) * SEQ_LDA + ks, SEQ_LDA);
                wmma::mma_sync(acc, a, bmat, acc);
            }
            __syncthreads();
        }
        wmma::store_matrix_sync(Gs + (mt * 16) * RPC + nt * 16, acc, RPC, wmma::mem_row_major);
        __syncthreads();

        // fused gate activations + cell update + h write
        for (int i = tid; i < BATCH * JPC; i += 256) {
            int b = i >> 3, j = i & 7;
            const float* gx = g_Gx + ((size_t)(t * NC + cb) * BATCH + b) * RPC;
            float fg = Gs[b * RPC + j]      + Bg[j]      + gx[j];
            float ig = Gs[b * RPC + 8 + j]  + Bg[8 + j]  + gx[8 + j];
            float cg = Gs[b * RPC + 16 + j] + Bg[16 + j] + gx[16 + j];
            float og = Gs[b * RPC + 24 + j] + Bg[24 + j] + gx[24 + j];
            float fs = 1.f / (1.f + __expf(-fg));
            float is = 1.f / (1.f + __expf(-ig));
            float os = 1.f / (1.f + __expf(-og));
            float cn = fs * Cs[i] + is * tanhf(cg);
            Cs[i] = cn;
            float h = os * tanhf(cn);
            int col = cb * JPC + j;
            __stcg(hwrite + b * HSZ + col, h);
            out[((size_t)t * BATCH + b) * HSZ + col] = h;
        }

        target += NC;
        grid_barrier(target);
    }
}

// ---------------- launch ----------------
extern "C" void kernel_launch(void* const* d_in, const int* in_sizes, int n_in,
                              void* d_out, int out_size)
{
    const float* x  = (const float*)d_in[0];
    const float* Wf = (const float*)d_in[1];
    const float* bf = (const float*)d_in[2];
    const float* Wi = (const float*)d_in[3];
    const float* bi = (const float*)d_in[4];
    const float* Wc = (const float*)d_in[5];
    const float* bc = (const float*)d_in[6];
    const float* Wo = (const float*)d_in[7];
    const float* bo = (const float*)d_in[8];
    float* out = (float*)d_out;

    cudaFuncSetAttribute(gx_kernel, cudaFuncAttributeMaxDynamicSharedMemorySize, GX_SMEM);
    cudaFuncSetAttribute(lstm_seq_kernel, cudaFuncAttributeMaxDynamicSharedMemorySize, SEQ_SMEM);

    reset_kernel<<<1, 1>>>();

    int n_pack = NC * HSZ * RPC + NC * ISZ * RPC + NC * RPC;
    pack_kernel<<<(n_pack + 255) / 256, 256>>>(Wf, Wi, Wc, Wo, bf, bi, bc, bo);

    dim3 ggrid(4096 / 128, (T_LEN * BATCH) / 128);   // (32, 256)
    gx_kernel<<<ggrid, 256, GX_SMEM>>>(x);

    lstm_seq_kernel<<<NC, 256, SEQ_SMEM>>>(out);

    (void)in_sizes; (void)n_in; (void)out_size;
}

// round 6
// speedup vs baseline: 1.2993x; 1.2993x over previous
#include <cuda_runtime.h>
#include <mma.h>
#include <cstdint>
#include <cstdio>

using namespace nvcuda;

#define T_LEN 512
#define BATCH 64
#define ISZ   512
#define HSZ   1024
#define HX    1536
#define NC    128      // c-groups == CTAs in sequential kernel
#define RPC   32       // gate rows per c-group (f8,i8,c8,o8)
#define JPC   8        // h columns per c-group

// ---------------- static device scratch (no cudaMalloc allowed) ----------------
__device__ float    g_Wrec[NC * HSZ * RPC];              // [c][k][r] tf32-rounded, 16 MB
__device__ float    g_Wx[NC * ISZ * RPC];                // [c][k][r] tf32-rounded, 8 MB
__device__ float    g_bg[NC * RPC];                      // packed biases
__device__ float    g_Gx[(size_t)T_LEN * NC * BATCH * RPC]; // [t][c][b][r], 512 MB
__device__ float    g_h[2 * BATCH * HSZ];                // double-buffered hidden state
__device__ unsigned g_bar;                               // grid barrier counter

__global__ void reset_kernel() { g_bar = 0u; }

// ---------------- pack: transpose weights into per-c k-major blocks ----------------
__global__ void pack_kernel(const float* __restrict__ Wf, const float* __restrict__ Wi,
                            const float* __restrict__ Wc, const float* __restrict__ Wo,
                            const float* __restrict__ bf, const float* __restrict__ bi,
                            const float* __restrict__ bc, const float* __restrict__ bo)
{
    int idx = blockIdx.x * blockDim.x + threadIdx.x;
    const int N1 = NC * HSZ * RPC;   // 4194304
    const int N2 = NC * ISZ * RPC;   // 2097152
    if (idx < N1) {
        int r = idx & 31; int k = (idx >> 5) & 1023; int c = idx >> 15;
        int gate = r >> 3; int j = c * JPC + (r & 7);
        const float* W = (gate == 0) ? Wf : (gate == 1) ? Wi : (gate == 2) ? Wc : Wo;
        g_Wrec[idx] = wmma::__float_to_tf32(W[(size_t)j * HX + k]);
    } else if (idx < N1 + N2) {
        int t2 = idx - N1;
        int r = t2 & 31; int k = (t2 >> 5) & 511; int c = t2 >> 14;
        int gate = r >> 3; int j = c * JPC + (r & 7);
        const float* W = (gate == 0) ? Wf : (gate == 1) ? Wi : (gate == 2) ? Wc : Wo;
        g_Wx[t2] = wmma::__float_to_tf32(W[(size_t)j * HX + HSZ + k]);
    } else if (idx < N1 + N2 + NC * RPC) {
        int t3 = idx - N1 - N2;
        int r = t3 & 31; int c = t3 >> 5;
        int gate = r >> 3; int j = c * JPC + (r & 7);
        const float* b = (gate == 0) ? bf : (gate == 1) ? bi : (gate == 2) ? bc : bo;
        g_bg[t3] = b[j];
    }
}

// ---------------- Gx = x @ Wx^T, written as [t][c][b][r] ----------------
#define GX_LDA 132
#define GX_SMEM (2 * 128 * GX_LDA * 4)

__global__ __launch_bounds__(256, 1) void gx_kernel(const float* __restrict__ x)
{
    extern __shared__ float sm[];
    float* As = sm;                   // 128 x 132
    float* Bs = sm + 128 * GX_LDA;    // 128 x 132
    int tid = threadIdx.x;
    int w = tid >> 5;
    int m0 = blockIdx.y * 128;        // 2 timesteps
    int n0 = blockIdx.x * 128;        // 4 c-groups
    int c0 = n0 >> 5;

    wmma::fragment<wmma::accumulator, 16, 16, 8, float> acc[8];
#pragma unroll
    for (int i = 0; i < 8; i++) wmma::fill_fragment(acc[i], 0.f);

    for (int kb = 0; kb < ISZ; kb += 128) {
        // stage A (x), tf32-rounded
#pragma unroll
        for (int it = 0; it < 16; ++it) {
            int p4 = tid + it * 256;
            int row = p4 >> 5, col4 = p4 & 31;
            float4 v = *(const float4*)(x + (size_t)(m0 + row) * ISZ + kb + col4 * 4);
            v.x = wmma::__float_to_tf32(v.x); v.y = wmma::__float_to_tf32(v.y);
            v.z = wmma::__float_to_tf32(v.z); v.w = wmma::__float_to_tf32(v.w);
            *(float4*)(As + row * GX_LDA + col4 * 4) = v;
        }
        // stage B (g_Wx already tf32-rounded); source blocks are contiguous
#pragma unroll
        for (int it = 0; it < 16; ++it) {
            int p4 = tid + it * 256;
            int cl = p4 >> 10; int rem = p4 & 1023;
            int k = rem >> 3; int r4 = rem & 7;
            float4 v = *(const float4*)(g_Wx + ((size_t)(c0 + cl) * ISZ + kb + k) * RPC + r4 * 4);
            *(float4*)(Bs + k * GX_LDA + cl * 32 + r4 * 4) = v;
        }
        __syncthreads();
#pragma unroll 4
        for (int ks = 0; ks < 128; ks += 8) {
            wmma::fragment<wmma::matrix_a, 16, 16, 8, wmma::precision::tf32, wmma::row_major> a;
            wmma::load_matrix_sync(a, As + (w * 16) * GX_LDA + ks, GX_LDA);
#pragma unroll
            for (int nt = 0; nt < 8; ++nt) {
                wmma::fragment<wmma::matrix_b, 16, 16, 8, wmma::precision::tf32, wmma::row_major> b;
                wmma::load_matrix_sync(b, Bs + ks * GX_LDA + nt * 16, GX_LDA);
                wmma::mma_sync(acc[nt], a, b, acc[nt]);
            }
        }
        __syncthreads();
    }
    // epilogue: m-tile of 16 stays inside a single timestep (64 | 16)
    int mg = m0 + w * 16;
    int t = mg >> 6; int b0 = mg & 63;
#pragma unroll
    for (int nt = 0; nt < 8; ++nt) {
        int ng = n0 + nt * 16;
        int c = ng >> 5; int r0 = ng & 31;
        float* dst = g_Gx + ((size_t)(t * NC + c) * BATCH + b0) * RPC + r0;
        wmma::store_matrix_sync(dst, acc[nt], RPC, wmma::mem_row_major);
    }
}

// ---------------- persistent sequential LSTM kernel (K-split across warps) ----------------
#define WS_LD   36                        // padded Ws leading dim (kills 128B bank aliasing)
#define SEQ_LDA 132                       // staged h leading dim
#define PS_LDB  36                        // partial buffer per-b stride
#define PS_LDW  (BATCH * PS_LDB)          // 2304 floats per warp partial
// floats: Ws 1024*36=36864 | A/Ps region max(2*64*132, 8*2304)=18432 | Cs 512 | Bg 32
#define SEQ_SMEM ((36864 + 18432 + 512 + 32) * 4)

__device__ __forceinline__ void grid_barrier(unsigned target)
{
    __syncthreads();
    if (threadIdx.x == 0) {
        __threadfence();
        atomicAdd(&g_bar, 1u);
        while (atomicAdd(&g_bar, 0u) < target) __nanosleep(32);
    }
    __syncthreads();
}

__global__ __launch_bounds__(256, 1) void lstm_seq_kernel(float* __restrict__ out)
{
    extern __shared__ float sm[];
    float* Ws  = sm;                         // [1024][36] Wh slice (tf32, padded) 144 KB
    float* Abase = sm + HSZ * WS_LD;         // union: {Ahi,Alo} / Ps
    float* Ahi = Abase;                      // [64][132] h hi chunk
    float* Alo = Abase + BATCH * SEQ_LDA;    // [64][132] h lo chunk
    float* Ps  = Abase;                      // [8][64][36] warp partials (after mma)
    float* Cs  = sm + HSZ * WS_LD + 18432;   // [512] cell state
    float* Bg  = Cs + BATCH * JPC;           // [32] biases

    int tid = threadIdx.x;
    int w = tid >> 5;
    int cb = blockIdx.x;

    // ---- init: copy Wh slice into padded SMEM, biases, zero state ----
    {
        const float4* wsrc = (const float4*)(g_Wrec + (size_t)cb * HSZ * RPC);
        for (int i = tid; i < HSZ * RPC / 4; i += 256) {
            int k = i >> 3, r4 = i & 7;
            ((float4*)(Ws + k * WS_LD))[r4] = wsrc[i];
        }
        if (tid < RPC) Bg[tid] = g_bg[cb * RPC + tid];
        for (int i = tid; i < BATCH * JPC; i += 256) {
            Cs[i] = 0.f;
            int b = i >> 3, j = i & 7;
            g_h[b * HSZ + cb * JPC + j] = 0.f;   // h_{-1} in buffer 0
        }
    }
    unsigned target = NC;
    grid_barrier(target);

    // pair indices for epilogue (each thread owns 2 (b,j) pairs)
    int p0 = tid * 2, p1 = tid * 2 + 1;
    int b_0 = p0 >> 3, j_0 = p0 & 7;
    int b_1 = p1 >> 3, j_1 = p1 & 7;

    for (int t = 0; t < T_LEN; ++t) {
        const float* hread = g_h + (size_t)(t & 1) * BATCH * HSZ;
        float* hwrite      = g_h + (size_t)((t + 1) & 1) * BATCH * HSZ;

        // prefetch this thread's Gx values (hides DRAM latency behind the MMA loop)
        float gxr[8];
        {
            const float* gxb = g_Gx + ((size_t)(t * NC + cb) * BATCH) * RPC;
            const float* g0 = gxb + b_0 * RPC + j_0;
            const float* g1 = gxb + b_1 * RPC + j_1;
            gxr[0] = __ldcg(g0);      gxr[1] = __ldcg(g0 + 8);
            gxr[2] = __ldcg(g0 + 16); gxr[3] = __ldcg(g0 + 24);
            gxr[4] = __ldcg(g1);      gxr[5] = __ldcg(g1 + 8);
            gxr[6] = __ldcg(g1 + 16); gxr[7] = __ldcg(g1 + 24);
        }

        // full 64x32 partial accumulator per warp (K-split across warps)
        wmma::fragment<wmma::accumulator, 16, 16, 8, float> acc[4][2];
#pragma unroll
        for (int mt = 0; mt < 4; ++mt)
#pragma unroll
            for (int nt = 0; nt < 2; ++nt) wmma::fill_fragment(acc[mt][nt], 0.f);

        for (int kb = 0; kb < 8; ++kb) {           // 8 staged chunks of K=128
            // stage h chunk as tf32 hi/lo (L2 reads, bypass stale L1)
#pragma unroll
            for (int it = 0; it < 8; ++it) {
                int p4 = tid + it * 256;
                int b = p4 >> 5, kk4 = p4 & 31;
                float4 v = __ldcg((const float4*)(hread + b * HSZ + kb * 128 + kk4 * 4));
                float4 hi, lo;
                hi.x = wmma::__float_to_tf32(v.x); lo.x = wmma::__float_to_tf32(v.x - hi.x);
                hi.y = wmma::__float_to_tf32(v.y); lo.y = wmma::__float_to_tf32(v.y - hi.y);
                hi.z = wmma::__float_to_tf32(v.z); lo.z = wmma::__float_to_tf32(v.z - hi.z);
                hi.w = wmma::__float_to_tf32(v.w); lo.w = wmma::__float_to_tf32(v.w - hi.w);
                *(float4*)(Ahi + b * SEQ_LDA + kk4 * 4) = hi;
                *(float4*)(Alo + b * SEQ_LDA + kk4 * 4) = lo;
            }
            __syncthreads();

            // this warp's 16-column K-sub-chunk
            const float* WsW = Ws + (kb * 128 + w * 16) * WS_LD;
            int ka = w * 16;
#pragma unroll
            for (int ks = 0; ks < 2; ++ks) {
                wmma::fragment<wmma::matrix_b, 16, 16, 8, wmma::precision::tf32, wmma::row_major> b0, b1;
                wmma::load_matrix_sync(b0, WsW + ks * 8 * WS_LD, WS_LD);
                wmma::load_matrix_sync(b1, WsW + ks * 8 * WS_LD + 16, WS_LD);
                wmma::fragment<wmma::matrix_a, 16, 16, 8, wmma::precision::tf32, wmma::row_major> a[4];
#pragma unroll
                for (int mt = 0; mt < 4; ++mt)
                    wmma::load_matrix_sync(a[mt], Ahi + (mt * 16) * SEQ_LDA + ka + ks * 8, SEQ_LDA);
#pragma unroll
                for (int mt = 0; mt < 4; ++mt) {
                    wmma::mma_sync(acc[mt][0], a[mt], b0, acc[mt][0]);
                    wmma::mma_sync(acc[mt][1], a[mt], b1, acc[mt][1]);
                }
#pragma unroll
                for (int mt = 0; mt < 4; ++mt)
                    wmma::load_matrix_sync(a[mt], Alo + (mt * 16) * SEQ_LDA + ka + ks * 8, SEQ_LDA);
#pragma unroll
                for (int mt = 0; mt < 4; ++mt) {
                    wmma::mma_sync(acc[mt][0], a[mt], b0, acc[mt][0]);
                    wmma::mma_sync(acc[mt][1], a[mt], b1, acc[mt][1]);
                }
            }
            __syncthreads();   // all warps done with this chunk before restage/overwrite
        }

        // store warp partials (Ps aliases Ahi/Alo; safe: synced after last chunk)
#pragma unroll
        for (int mt = 0; mt < 4; ++mt)
#pragma unroll
            for (int nt = 0; nt < 2; ++nt)
                wmma::store_matrix_sync(Ps + w * PS_LDW + (mt * 16) * PS_LDB + nt * 16,
                                        acc[mt][nt], PS_LDB, wmma::mem_row_major);
        __syncthreads();

        // reduce 8 partials + fused gate activations + cell update + h write
#pragma unroll
        for (int q = 0; q < 2; ++q) {
            int p = q ? p1 : p0;
            int b = q ? b_1 : b_0;
            int j = q ? j_1 : j_0;
            float s0 = 0.f, s1 = 0.f, s2 = 0.f, s3 = 0.f;
#pragma unroll
            for (int ww = 0; ww < 8; ++ww) {
                const float* base = Ps + ww * PS_LDW + b * PS_LDB + j;
                s0 += base[0]; s1 += base[8]; s2 += base[16]; s3 += base[24];
            }
            float fg = s0 + Bg[j]      + gxr[q * 4 + 0];
            float ig = s1 + Bg[8 + j]  + gxr[q * 4 + 1];
            float cg = s2 + Bg[16 + j] + gxr[q * 4 + 2];
            float og = s3 + Bg[24 + j] + gxr[q * 4 + 3];
            float fs = 1.f / (1.f + __expf(-fg));
            float is = 1.f / (1.f + __expf(-ig));
            float os = 1.f / (1.f + __expf(-og));
            float cn = fs * Cs[p] + is * tanhf(cg);
            Cs[p] = cn;
            float h = os * tanhf(cn);
            int col = cb * JPC + j;
            __stcg(hwrite + b * HSZ + col, h);
            out[((size_t)t * BATCH + b) * HSZ + col] = h;
        }

        target += NC;
        grid_barrier(target);
    }
}

// ---------------- launch ----------------
extern "C" void kernel_launch(void* const* d_in, const int* in_sizes, int n_in,
                              void* d_out, int out_size)
{
    const float* x  = (const float*)d_in[0];
    const float* Wf = (const float*)d_in[1];
    const float* bf = (const float*)d_in[2];
    const float* Wi = (const float*)d_in[3];
    const float* bi = (const float*)d_in[4];
    const float* Wc = (const float*)d_in[5];
    const float* bc = (const float*)d_in[6];
    const float* Wo = (const float*)d_in[7];
    const float* bo = (const float*)d_in[8];
    float* out = (float*)d_out;

    cudaFuncSetAttribute(gx_kernel, cudaFuncAttributeMaxDynamicSharedMemorySize, GX_SMEM);
    cudaFuncSetAttribute(lstm_seq_kernel, cudaFuncAttributeMaxDynamicSharedMemorySize, SEQ_SMEM);

    reset_kernel<<<1, 1>>>();

    int n_pack = NC * HSZ * RPC + NC * ISZ * RPC + NC * RPC;
    pack_kernel<<<(n_pack + 255) / 256, 256>>>(Wf, Wi, Wc, Wo, bf, bi, bc, bo);

    dim3 ggrid(4096 / 128, (T_LEN * BATCH) / 128);   // (32, 256)
    gx_kernel<<<ggrid, 256, GX_SMEM>>>(x);

    lstm_seq_kernel<<<NC, 256, SEQ_SMEM>>>(out);

    (void)in_sizes; (void)n_in; (void)out_size;
}

// round 9
// speedup vs baseline: 1.3348x; 1.0274x over previous
#include <cuda_runtime.h>
#include <mma.h>
#include <cstdint>
#include <cstdio>

using namespace nvcuda;

#define T_LEN 512
#define BATCH 64
#define ISZ   512
#define HSZ   1024
#define HX    1536
#define NC    128      // c-groups == CTAs in sequential kernel
#define RPC   32       // gate rows per c-group (f8,i8,c8,o8)
#define JPC   8        // h columns per c-group

// ---------------- static device scratch (no cudaMalloc allowed) ----------------
__device__ float    g_Wrec[NC * HSZ * RPC];              // [c][k][r] tf32-rounded, 16 MB
__device__ float    g_Wx[NC * ISZ * RPC];                // [c][k][r] tf32-rounded, 8 MB
__device__ float    g_bg[NC * RPC];                      // packed biases
__device__ float    g_Gx[(size_t)T_LEN * NC * BATCH * RPC]; // [t][c][b][r], 512 MB
__device__ float    g_h[2 * BATCH * HSZ];                // double-buffered hidden state
__device__ unsigned g_flags[8];                          // per-chunk cumulative arrival counters

__global__ void reset_kernel() { if (threadIdx.x < 8) g_flags[threadIdx.x] = 0u; }

// ---------------- pack: transpose weights into per-c k-major blocks ----------------
__global__ void pack_kernel(const float* __restrict__ Wf, const float* __restrict__ Wi,
                            const float* __restrict__ Wc, const float* __restrict__ Wo,
                            const float* __restrict__ bf, const float* __restrict__ bi,
                            const float* __restrict__ bc, const float* __restrict__ bo)
{
    int idx = blockIdx.x * blockDim.x + threadIdx.x;
    const int N1 = NC * HSZ * RPC;   // 4194304
    const int N2 = NC * ISZ * RPC;   // 2097152
    if (idx < N1) {
        int r = idx & 31; int k = (idx >> 5) & 1023; int c = idx >> 15;
        int gate = r >> 3; int j = c * JPC + (r & 7);
        const float* W = (gate == 0) ? Wf : (gate == 1) ? Wi : (gate == 2) ? Wc : Wo;
        g_Wrec[idx] = wmma::__float_to_tf32(W[(size_t)j * HX + k]);
    } else if (idx < N1 + N2) {
        int t2 = idx - N1;
        int r = t2 & 31; int k = (t2 >> 5) & 511; int c = t2 >> 14;
        int gate = r >> 3; int j = c * JPC + (r & 7);
        const float* W = (gate == 0) ? Wf : (gate == 1) ? Wi : (gate == 2) ? Wc : Wo;
        g_Wx[t2] = wmma::__float_to_tf32(W[(size_t)j * HX + HSZ + k]);
    } else if (idx < N1 + N2 + NC * RPC) {
        int t3 = idx - N1 - N2;
        int r = t3 & 31; int c = t3 >> 5;
        int gate = r >> 3; int j = c * JPC + (r & 7);
        const float* b = (gate == 0) ? bf : (gate == 1) ? bi : (gate == 2) ? bc : bo;
        g_bg[t3] = b[j];
    }
}

// ---------------- Gx = x @ Wx^T, written as [t][c][b][r] ----------------
#define GX_LDA 132
#define GX_SMEM (2 * 128 * GX_LDA * 4)

__global__ __launch_bounds__(256, 1) void gx_kernel(const float* __restrict__ x)
{
    extern __shared__ float sm[];
    float* As = sm;                   // 128 x 132
    float* Bs = sm + 128 * GX_LDA;    // 128 x 132
    int tid = threadIdx.x;
    int w = tid >> 5;
    int m0 = blockIdx.y * 128;        // 2 timesteps
    int n0 = blockIdx.x * 128;        // 4 c-groups
    int c0 = n0 >> 5;

    wmma::fragment<wmma::accumulator, 16, 16, 8, float> acc[8];
#pragma unroll
    for (int i = 0; i < 8; i++) wmma::fill_fragment(acc[i], 0.f);

    for (int kb = 0; kb < ISZ; kb += 128) {
#pragma unroll
        for (int it = 0; it < 16; ++it) {
            int p4 = tid + it * 256;
            int row = p4 >> 5, col4 = p4 & 31;
            float4 v = *(const float4*)(x + (size_t)(m0 + row) * ISZ + kb + col4 * 4);
            v.x = wmma::__float_to_tf32(v.x); v.y = wmma::__float_to_tf32(v.y);
            v.z = wmma::__float_to_tf32(v.z); v.w = wmma::__float_to_tf32(v.w);
            *(float4*)(As + row * GX_LDA + col4 * 4) = v;
        }
#pragma unroll
        for (int it = 0; it < 16; ++it) {
            int p4 = tid + it * 256;
            int cl = p4 >> 10; int rem = p4 & 1023;
            int k = rem >> 3; int r4 = rem & 7;
            float4 v = *(const float4*)(g_Wx + ((size_t)(c0 + cl) * ISZ + kb + k) * RPC + r4 * 4);
            *(float4*)(Bs + k * GX_LDA + cl * 32 + r4 * 4) = v;
        }
        __syncthreads();
#pragma unroll 4
        for (int ks = 0; ks < 128; ks += 8) {
            wmma::fragment<wmma::matrix_a, 16, 16, 8, wmma::precision::tf32, wmma::row_major> a;
            wmma::load_matrix_sync(a, As + (w * 16) * GX_LDA + ks, GX_LDA);
#pragma unroll
            for (int nt = 0; nt < 8; ++nt) {
                wmma::fragment<wmma::matrix_b, 16, 16, 8, wmma::precision::tf32, wmma::row_major> b;
                wmma::load_matrix_sync(b, Bs + ks * GX_LDA + nt * 16, GX_LDA);
                wmma::mma_sync(acc[nt], a, b, acc[nt]);
            }
        }
        __syncthreads();
    }
    int mg = m0 + w * 16;
    int t = mg >> 6; int b0 = mg & 63;
#pragma unroll
    for (int nt = 0; nt < 8; ++nt) {
        int ng = n0 + nt * 16;
        int c = ng >> 5; int r0 = ng & 31;
        float* dst = g_Gx + ((size_t)(t * NC + c) * BATCH + b0) * RPC + r0;
        wmma::store_matrix_sync(dst, acc[nt], RPC, wmma::mem_row_major);
    }
}

// ---------------- persistent sequential LSTM kernel ----------------
// Warp w owns K-columns [w*128, (w+1)*128): stages its own A sub-chunks (warp-private
// SMEM, no block syncs in the MMA loop) and waits only on flag[w].
#define WS_LD     36                       // Ws leading dim (144B rows, 16B aligned)
#define A_LD      20                       // per-warp A sub-chunk leading dim (80B rows)
#define AW_STRIDE (2 * 64 * A_LD)          // floats per warp (hi + lo) = 2560
#define PS_LD     36                       // MUST be multiple of 4 (wmma float ldm rule)
#define PS_W      (64 * PS_LD)             // 2304 floats per warp partial
#define SEQ_SMEM  ((HSZ * WS_LD + 8 * AW_STRIDE) * 4)   // 229,376 B  (Ps: 8*2304=18432 fits)

__global__ __launch_bounds__(256, 1) void lstm_seq_kernel(float* __restrict__ out)
{
    extern __shared__ float sm[];
    float* Ws    = sm;                         // [1024][36] Wh slice (tf32, padded)
    float* Abase = sm + HSZ * WS_LD;           // per-warp A buffers; aliased by Ps
    float* Ps    = Abase;                      // [8][64][36] warp partials (epilogue only)

    int tid  = threadIdx.x;
    int w    = tid >> 5;
    int lane = tid & 31;
    int cb   = blockIdx.x;

    float* AhiW = Abase + w * AW_STRIDE;       // [64][20]
    float* AloW = AhiW + 64 * A_LD;            // [64][20]

    // ---- init: Ws copy (padded), per-thread bias/cell regs, zero h_{-1} ----
    {
        const float4* wsrc = (const float4*)(g_Wrec + (size_t)cb * HSZ * RPC);
        for (int i = tid; i < HSZ * RPC / 4; i += 256) {
            int k = i >> 3, r4 = i & 7;
            ((float4*)(Ws + k * WS_LD))[r4] = wsrc[i];
        }
    }
    int b  = tid >> 2;                 // batch row owned (4 threads per b)
    int j0 = (2 * tid) & 7;            // even j; this thread owns (b,j0),(b,j0+1)
    float bias[8];
    {
        const float* bg = g_bg + cb * RPC;
        bias[0] = bg[j0];      bias[1] = bg[8 + j0];
        bias[2] = bg[16 + j0]; bias[3] = bg[24 + j0];
        bias[4] = bg[j0 + 1];      bias[5] = bg[8 + j0 + 1];
        bias[6] = bg[16 + j0 + 1]; bias[7] = bg[24 + j0 + 1];
    }
    float cell0 = 0.f, cell1 = 0.f;
    {
        float2 z; z.x = 0.f; z.y = 0.f;
        __stcg((float2*)(g_h + b * HSZ + cb * JPC + j0), z);   // h_{-1} in buffer 0
    }
    __syncthreads();
    if (tid == 0) { __threadfence(); atomicAdd(&g_flags[cb >> 4], 1u); }

    int r0row = lane >> 2;             // staging: row sub-index
    int c4    = lane & 3;              // staging: col group (4 floats)

    for (int t = 0; t < T_LEN; ++t) {
        const float* hread = g_h + (size_t)(t & 1) * BATCH * HSZ;
        float* hwrite      = g_h + (size_t)((t + 1) & 1) * BATCH * HSZ;

        // prefetch Gx early (independent of flag) to hide DRAM latency
        const float* gxb = g_Gx + ((size_t)(t * NC + cb) * BATCH + b) * RPC;
        float2 gx0 = __ldcg((const float2*)(gxb + j0));
        float2 gx1 = __ldcg((const float2*)(gxb + 8 + j0));
        float2 gx2 = __ldcg((const float2*)(gxb + 16 + j0));
        float2 gx3 = __ldcg((const float2*)(gxb + 24 + j0));

        // per-warp wait: chunk w of h_{t-1} fully written (16 producer CTAs)
        {
            unsigned tgt = 16u * (unsigned)(t + 1);
            unsigned v;
            for (;;) {
                asm volatile("ld.global.cg.u32 %0, [%1];" : "=r"(v) : "l"(g_flags + w) : "memory");
                if (v >= tgt) break;
                __nanosleep(32);
            }
            __threadfence();
        }

        wmma::fragment<wmma::accumulator, 16, 16, 8, float> acc[4][2];
#pragma unroll
        for (int mt = 0; mt < 4; ++mt)
#pragma unroll
            for (int nt = 0; nt < 2; ++nt) wmma::fill_fragment(acc[mt][nt], 0.f);

        const float* hw = hread + w * 128;

        // prologue: load sub-chunk 0 into registers
        float4 rg[8];
#pragma unroll
        for (int p = 0; p < 8; ++p)
            rg[p] = __ldcg((const float4*)(hw + (size_t)(p * 8 + r0row) * HSZ + c4 * 4));

        for (int s = 0; s < 8; ++s) {
            // convert hi/lo tf32 + STS into warp-private buffer
#pragma unroll
            for (int p = 0; p < 8; ++p) {
                float4 v = rg[p], hi, lo;
                hi.x = wmma::__float_to_tf32(v.x); lo.x = wmma::__float_to_tf32(v.x - hi.x);
                hi.y = wmma::__float_to_tf32(v.y); lo.y = wmma::__float_to_tf32(v.y - hi.y);
                hi.z = wmma::__float_to_tf32(v.z); lo.z = wmma::__float_to_tf32(v.z - hi.z);
                hi.w = wmma::__float_to_tf32(v.w); lo.w = wmma::__float_to_tf32(v.w - hi.w);
                int row = p * 8 + r0row;
                *(float4*)(AhiW + row * A_LD + c4 * 4) = hi;
                *(float4*)(AloW + row * A_LD + c4 * 4) = lo;
            }
            // register-prefetch next sub-chunk (L2 latency hidden behind MMA below)
            if (s < 7) {
#pragma unroll
                for (int p = 0; p < 8; ++p)
                    rg[p] = __ldcg((const float4*)(hw + (size_t)(p * 8 + r0row) * HSZ
                                                   + (s + 1) * 16 + c4 * 4));
            }
            __syncwarp();   // STS visible to all lanes before warp-collective loads

            const float* WsW = Ws + (size_t)(w * 128 + s * 16) * WS_LD;
#pragma unroll
            for (int ks = 0; ks < 2; ++ks) {
                wmma::fragment<wmma::matrix_b, 16, 16, 8, wmma::precision::tf32, wmma::row_major> b0, b1;
                wmma::load_matrix_sync(b0, WsW + ks * 8 * WS_LD, WS_LD);
                wmma::load_matrix_sync(b1, WsW + ks * 8 * WS_LD + 16, WS_LD);
                wmma::fragment<wmma::matrix_a, 16, 16, 8, wmma::precision::tf32, wmma::row_major> a[4];
#pragma unroll
                for (int mt = 0; mt < 4; ++mt)
                    wmma::load_matrix_sync(a[mt], AhiW + (mt * 16) * A_LD + ks * 8, A_LD);
#pragma unroll
                for (int mt = 0; mt < 4; ++mt) {
                    wmma::mma_sync(acc[mt][0], a[mt], b0, acc[mt][0]);
                    wmma::mma_sync(acc[mt][1], a[mt], b1, acc[mt][1]);
                }
#pragma unroll
                for (int mt = 0; mt < 4; ++mt)
                    wmma::load_matrix_sync(a[mt], AloW + (mt * 16) * A_LD + ks * 8, A_LD);
#pragma unroll
                for (int mt = 0; mt < 4; ++mt) {
                    wmma::mma_sync(acc[mt][0], a[mt], b0, acc[mt][0]);
                    wmma::mma_sync(acc[mt][1], a[mt], b1, acc[mt][1]);
                }
            }
        }

        __syncthreads();   // all warps done with A buffers; Ps region free
#pragma unroll
        for (int mt = 0; mt < 4; ++mt)
#pragma unroll
            for (int nt = 0; nt < 2; ++nt)
                wmma::store_matrix_sync(Ps + w * PS_W + (mt * 16) * PS_LD + nt * 16,
                                        acc[mt][nt], PS_LD, wmma::mem_row_major);
        __syncthreads();

        // reduce 8 warp-partials + fused activations + cell update + h/out write
        {
            float s0 = 0.f, s1 = 0.f, s2 = 0.f, s3 = 0.f;
            float u0 = 0.f, u1 = 0.f, u2 = 0.f, u3 = 0.f;
#pragma unroll
            for (int ww = 0; ww < 8; ++ww) {
                const float* base = Ps + ww * PS_W + b * PS_LD + j0;
                s0 += base[0];  s1 += base[8];  s2 += base[16]; s3 += base[24];
                u0 += base[1];  u1 += base[9];  u2 += base[17]; u3 += base[25];
            }
            float fg0 = s0 + bias[0] + gx0.x, fg1 = u0 + bias[4] + gx0.y;
            float ig0 = s1 + bias[1] + gx1.x, ig1 = u1 + bias[5] + gx1.y;
            float cg0 = s2 + bias[2] + gx2.x, cg1 = u2 + bias[6] + gx2.y;
            float og0 = s3 + bias[3] + gx3.x, og1 = u3 + bias[7] + gx3.y;
            float fs0 = 1.f / (1.f + __expf(-fg0)), fs1 = 1.f / (1.f + __expf(-fg1));
            float is0 = 1.f / (1.f + __expf(-ig0)), is1 = 1.f / (1.f + __expf(-ig1));
            float os0 = 1.f / (1.f + __expf(-og0)), os1 = 1.f / (1.f + __expf(-og1));
            cell0 = fs0 * cell0 + is0 * tanhf(cg0);
            cell1 = fs1 * cell1 + is1 * tanhf(cg1);
            float2 hv;
            hv.x = os0 * tanhf(cell0);
            hv.y = os1 * tanhf(cell1);
            __stcg((float2*)(hwrite + b * HSZ + cb * JPC + j0), hv);
            *(float2*)(out + ((size_t)t * BATCH + b) * HSZ + cb * JPC + j0) = hv;
        }

        __syncthreads();
        if (tid == 0) { __threadfence(); atomicAdd(g_flags + (cb >> 4), 1u); }
    }
}

// ---------------- launch ----------------
extern "C" void kernel_launch(void* const* d_in, const int* in_sizes, int n_in,
                              void* d_out, int out_size)
{
    const float* x  = (const float*)d_in[0];
    const float* Wf = (const float*)d_in[1];
    const float* bf = (const float*)d_in[2];
    const float* Wi = (const float*)d_in[3];
    const float* bi = (const float*)d_in[4];
    const float* Wc = (const float*)d_in[5];
    const float* bc = (const float*)d_in[6];
    const float* Wo = (const float*)d_in[7];
    const float* bo = (const float*)d_in[8];
    float* out = (float*)d_out;

    cudaFuncSetAttribute(gx_kernel, cudaFuncAttributeMaxDynamicSharedMemorySize, GX_SMEM);
    cudaFuncSetAttribute(lstm_seq_kernel, cudaFuncAttributeMaxDynamicSharedMemorySize, SEQ_SMEM);

    reset_kernel<<<1, 32>>>();

    int n_pack = NC * HSZ * RPC + NC * ISZ * RPC + NC * RPC;
    pack_kernel<<<(n_pack + 255) / 256, 256>>>(Wf, Wi, Wc, Wo, bf, bi, bc, bo);

    dim3 ggrid(4096 / 128, (T_LEN * BATCH) / 128);   // (32, 256)
    gx_kernel<<<ggrid, 256, GX_SMEM>>>(x);

    lstm_seq_kernel<<<NC, 256, SEQ_SMEM>>>(out);

    (void)in_sizes; (void)n_in; (void)out_size;
}

// round 10
// speedup vs baseline: 1.4779x; 1.1072x over previous
#include <cuda_runtime.h>
#include <mma.h>
#include <cstdint>
#include <cstdio>

using namespace nvcuda;

#define T_LEN 512
#define BATCH 64
#define ISZ   512
#define HSZ   1024
#define HX    1536
#define NC    128      // c-groups == CTAs in sequential kernel
#define RPC   32       // gate rows per c-group (f8,i8,c8,o8)
#define JPC   8        // h columns per c-group

// ---------------- static device scratch (no cudaMalloc allowed) ----------------
__device__ float    g_Wrec[NC * HSZ * RPC];              // [c][k][r] tf32-rounded, 16 MB
__device__ float    g_Wx[NC * ISZ * RPC];                // [c][k][r] tf32-rounded, 8 MB
__device__ float    g_bg[NC * RPC];                      // packed biases
__device__ float    g_Gx[(size_t)T_LEN * NC * BATCH * RPC]; // [t][c][b][r], 512 MB
__device__ float    g_h[2 * BATCH * HSZ];                // double-buffered hidden state
__device__ unsigned g_flags[8];                          // per-chunk cumulative arrival counters

__global__ void reset_kernel() { if (threadIdx.x < 8) g_flags[threadIdx.x] = 0u; }

// ---------------- pack: transpose weights into per-c k-major blocks ----------------
__global__ void pack_kernel(const float* __restrict__ Wf, const float* __restrict__ Wi,
                            const float* __restrict__ Wc, const float* __restrict__ Wo,
                            const float* __restrict__ bf, const float* __restrict__ bi,
                            const float* __restrict__ bc, const float* __restrict__ bo)
{
    int idx = blockIdx.x * blockDim.x + threadIdx.x;
    const int N1 = NC * HSZ * RPC;   // 4194304
    const int N2 = NC * ISZ * RPC;   // 2097152
    if (idx < N1) {
        int r = idx & 31; int k = (idx >> 5) & 1023; int c = idx >> 15;
        int gate = r >> 3; int j = c * JPC + (r & 7);
        const float* W = (gate == 0) ? Wf : (gate == 1) ? Wi : (gate == 2) ? Wc : Wo;
        g_Wrec[idx] = wmma::__float_to_tf32(W[(size_t)j * HX + k]);
    } else if (idx < N1 + N2) {
        int t2 = idx - N1;
        int r = t2 & 31; int k = (t2 >> 5) & 511; int c = t2 >> 14;
        int gate = r >> 3; int j = c * JPC + (r & 7);
        const float* W = (gate == 0) ? Wf : (gate == 1) ? Wi : (gate == 2) ? Wc : Wo;
        g_Wx[t2] = wmma::__float_to_tf32(W[(size_t)j * HX + HSZ + k]);
    } else if (idx < N1 + N2 + NC * RPC) {
        int t3 = idx - N1 - N2;
        int r = t3 & 31; int c = t3 >> 5;
        int gate = r >> 3; int j = c * JPC + (r & 7);
        const float* b = (gate == 0) ? bf : (gate == 1) ? bi : (gate == 2) ? bc : bo;
        g_bg[t3] = b[j];
    }
}

// ---------------- Gx = x @ Wx^T, written as [t][c][b][r] ----------------
#define GX_LDA 132
#define GX_SMEM (2 * 128 * GX_LDA * 4)

__global__ __launch_bounds__(256, 1) void gx_kernel(const float* __restrict__ x)
{
    extern __shared__ float sm[];
    float* As = sm;                   // 128 x 132
    float* Bs = sm + 128 * GX_LDA;    // 128 x 132
    int tid = threadIdx.x;
    int w = tid >> 5;
    int m0 = blockIdx.y * 128;        // 2 timesteps
    int n0 = blockIdx.x * 128;        // 4 c-groups
    int c0 = n0 >> 5;

    wmma::fragment<wmma::accumulator, 16, 16, 8, float> acc[8];
#pragma unroll
    for (int i = 0; i < 8; i++) wmma::fill_fragment(acc[i], 0.f);

    for (int kb = 0; kb < ISZ; kb += 128) {
#pragma unroll
        for (int it = 0; it < 16; ++it) {
            int p4 = tid + it * 256;
            int row = p4 >> 5, col4 = p4 & 31;
            float4 v = *(const float4*)(x + (size_t)(m0 + row) * ISZ + kb + col4 * 4);
            v.x = wmma::__float_to_tf32(v.x); v.y = wmma::__float_to_tf32(v.y);
            v.z = wmma::__float_to_tf32(v.z); v.w = wmma::__float_to_tf32(v.w);
            *(float4*)(As + row * GX_LDA + col4 * 4) = v;
        }
#pragma unroll
        for (int it = 0; it < 16; ++it) {
            int p4 = tid + it * 256;
            int cl = p4 >> 10; int rem = p4 & 1023;
            int k = rem >> 3; int r4 = rem & 7;
            float4 v = *(const float4*)(g_Wx + ((size_t)(c0 + cl) * ISZ + kb + k) * RPC + r4 * 4);
            *(float4*)(Bs + k * GX_LDA + cl * 32 + r4 * 4) = v;
        }
        __syncthreads();
#pragma unroll 4
        for (int ks = 0; ks < 128; ks += 8) {
            wmma::fragment<wmma::matrix_a, 16, 16, 8, wmma::precision::tf32, wmma::row_major> a;
            wmma::load_matrix_sync(a, As + (w * 16) * GX_LDA + ks, GX_LDA);
#pragma unroll
            for (int nt = 0; nt < 8; ++nt) {
                wmma::fragment<wmma::matrix_b, 16, 16, 8, wmma::precision::tf32, wmma::row_major> b;
                wmma::load_matrix_sync(b, Bs + ks * GX_LDA + nt * 16, GX_LDA);
                wmma::mma_sync(acc[nt], a, b, acc[nt]);
            }
        }
        __syncthreads();
    }
    int mg = m0 + w * 16;
    int t = mg >> 6; int b0 = mg & 63;
#pragma unroll
    for (int nt = 0; nt < 8; ++nt) {
        int ng = n0 + nt * 16;
        int c = ng >> 5; int r0 = ng & 31;
        float* dst = g_Gx + ((size_t)(t * NC + c) * BATCH + b0) * RPC + r0;
        wmma::store_matrix_sync(dst, acc[nt], RPC, wmma::mem_row_major);
    }
}

// ---------------- persistent sequential LSTM kernel ----------------
// 512 threads = 16 warps. Warp (mh = w>>3, kw = w&7) owns M rows [mh*32, mh*32+32)
// and K columns [kw*128, (kw+1)*128). Warp-private A staging; no block syncs in the
// MMA loop; acquire/release flag protocol (no threadfence).
#define WS_LD     36                       // Ws leading dim
#define A_LD      20                       // A sub-chunk leading dim (80B rows)
#define AW_STRIDE (2 * 32 * A_LD)          // floats per warp (hi + lo) = 1280
#define PS_LD     36                       // multiple of 4 (wmma float ldm rule)
#define PS_CH     (64 * PS_LD)             // 2304 floats per kw-chunk partial
#define SEQ_SMEM  ((HSZ * WS_LD + 16 * AW_STRIDE) * 4)   // 229,376 B

__device__ __forceinline__ unsigned ld_acquire(const unsigned* p)
{
    unsigned v;
    asm volatile("ld.acquire.gpu.global.u32 %0, [%1];" : "=r"(v) : "l"(p) : "memory");
    return v;
}
__device__ __forceinline__ void red_release_add(unsigned* p, unsigned v)
{
    asm volatile("red.release.gpu.global.add.u32 [%0], %1;" :: "l"(p), "r"(v) : "memory");
}

__global__ __launch_bounds__(512, 1) void lstm_seq_kernel(float* __restrict__ out)
{
    extern __shared__ float sm[];
    float* Ws    = sm;                         // [1024][36] Wh slice (tf32, padded)
    float* Abase = sm + HSZ * WS_LD;           // per-warp A buffers; aliased by Ps
    float* Ps    = Abase;                      // [8][64][36] chunk partials (epilogue only)

    int tid  = threadIdx.x;
    int w    = tid >> 5;
    int lane = tid & 31;
    int kw   = w & 7;                  // K-chunk owned
    int mh   = w >> 3;                 // M half owned
    int cb   = blockIdx.x;

    float* AhiW = Abase + w * AW_STRIDE;       // [32][20]
    float* AloW = AhiW + 32 * A_LD;            // [32][20]

    // ---- init: Ws copy (padded), per-thread bias/cell regs, zero h_{-1} ----
    {
        const float4* wsrc = (const float4*)(g_Wrec + (size_t)cb * HSZ * RPC);
        for (int i = tid; i < HSZ * RPC / 4; i += 512) {
            int k = i >> 3, r4 = i & 7;
            ((float4*)(Ws + k * WS_LD))[r4] = wsrc[i];
        }
    }
    int b = tid >> 3;                  // batch row owned (8 threads per b)
    int j = tid & 7;                   // h column owned: exactly one (b,j) per thread
    float bias0, bias1, bias2, bias3;
    {
        const float* bg = g_bg + cb * RPC;
        bias0 = bg[j]; bias1 = bg[8 + j]; bias2 = bg[16 + j]; bias3 = bg[24 + j];
    }
    float cell = 0.f;
    __stcg(g_h + b * HSZ + cb * JPC + j, 0.f);   // h_{-1} in buffer 0
    __syncthreads();
    if (tid == 0) red_release_add(&g_flags[cb >> 4], 1u);

    int r0row = lane >> 2;             // staging: row sub-index (0..7)
    int c4    = lane & 3;              // staging: col group (4 floats)
    int mbase = mh * 32;               // this warp's global M offset

    for (int t = 0; t < T_LEN; ++t) {
        const float* hread = g_h + (size_t)(t & 1) * BATCH * HSZ;
        float* hwrite      = g_h + (size_t)((t + 1) & 1) * BATCH * HSZ;

        // prefetch Gx early (independent of flag) to hide DRAM latency
        const float* gxb = g_Gx + ((size_t)(t * NC + cb) * BATCH + b) * RPC;
        float gx0 = __ldcg(gxb + j);
        float gx1 = __ldcg(gxb + 8 + j);
        float gx2 = __ldcg(gxb + 16 + j);
        float gx3 = __ldcg(gxb + 24 + j);

        // per-warp wait: chunk kw of h_{t-1} fully written (16 producer CTAs)
        {
            unsigned tgt = 16u * (unsigned)(t + 1);
            while (ld_acquire(g_flags + kw) < tgt) __nanosleep(32);
        }

        wmma::fragment<wmma::accumulator, 16, 16, 8, float> acc[2][2];
#pragma unroll
        for (int mt = 0; mt < 2; ++mt)
#pragma unroll
            for (int nt = 0; nt < 2; ++nt) wmma::fill_fragment(acc[mt][nt], 0.f);

        const float* hw = hread + kw * 128;

        // prologue: load sub-chunk 0 into registers (4 rows-of-8 per lane group)
        float4 rg[4];
#pragma unroll
        for (int p = 0; p < 4; ++p)
            rg[p] = __ldcg((const float4*)(hw + (size_t)(mbase + p * 8 + r0row) * HSZ + c4 * 4));

        for (int s = 0; s < 8; ++s) {
            // hi = tf32-rounded; lo = residual fed raw (HMMA reads top bits only)
#pragma unroll
            for (int p = 0; p < 4; ++p) {
                float4 v = rg[p], hi, lo;
                hi.x = wmma::__float_to_tf32(v.x); lo.x = v.x - hi.x;
                hi.y = wmma::__float_to_tf32(v.y); lo.y = v.y - hi.y;
                hi.z = wmma::__float_to_tf32(v.z); lo.z = v.z - hi.z;
                hi.w = wmma::__float_to_tf32(v.w); lo.w = v.w - hi.w;
                int row = p * 8 + r0row;
                *(float4*)(AhiW + row * A_LD + c4 * 4) = hi;
                *(float4*)(AloW + row * A_LD + c4 * 4) = lo;
            }
            // register-prefetch next sub-chunk (L2 latency hidden behind MMA below)
            if (s < 7) {
#pragma unroll
                for (int p = 0; p < 4; ++p)
                    rg[p] = __ldcg((const float4*)(hw + (size_t)(mbase + p * 8 + r0row) * HSZ
                                                   + (s + 1) * 16 + c4 * 4));
            }
            __syncwarp();   // STS visible to all lanes before warp-collective loads

            const float* WsW = Ws + (size_t)(kw * 128 + s * 16) * WS_LD;
#pragma unroll
            for (int ks = 0; ks < 2; ++ks) {
                wmma::fragment<wmma::matrix_b, 16, 16, 8, wmma::precision::tf32, wmma::row_major> b0, b1;
                wmma::load_matrix_sync(b0, WsW + ks * 8 * WS_LD, WS_LD);
                wmma::load_matrix_sync(b1, WsW + ks * 8 * WS_LD + 16, WS_LD);
                wmma::fragment<wmma::matrix_a, 16, 16, 8, wmma::precision::tf32, wmma::row_major> a[2];
#pragma unroll
                for (int mt = 0; mt < 2; ++mt)
                    wmma::load_matrix_sync(a[mt], AhiW + (mt * 16) * A_LD + ks * 8, A_LD);
#pragma unroll
                for (int mt = 0; mt < 2; ++mt) {
                    wmma::mma_sync(acc[mt][0], a[mt], b0, acc[mt][0]);
                    wmma::mma_sync(acc[mt][1], a[mt], b1, acc[mt][1]);
                }
#pragma unroll
                for (int mt = 0; mt < 2; ++mt)
                    wmma::load_matrix_sync(a[mt], AloW + (mt * 16) * A_LD + ks * 8, A_LD);
#pragma unroll
                for (int mt = 0; mt < 2; ++mt) {
                    wmma::mma_sync(acc[mt][0], a[mt], b0, acc[mt][0]);
                    wmma::mma_sync(acc[mt][1], a[mt], b1, acc[mt][1]);
                }
            }
        }

        __syncthreads();   // all warps done with A buffers; Ps region free
#pragma unroll
        for (int mt = 0; mt < 2; ++mt)
#pragma unroll
            for (int nt = 0; nt < 2; ++nt)
                wmma::store_matrix_sync(Ps + kw * PS_CH + (mbase + mt * 16) * PS_LD + nt * 16,
                                        acc[mt][nt], PS_LD, wmma::mem_row_major);
        __syncthreads();

        // reduce 8 chunk-partials + fused activations + cell update + h/out write
        {
            float s0 = 0.f, s1 = 0.f, s2 = 0.f, s3 = 0.f;
#pragma unroll
            for (int ww = 0; ww < 8; ++ww) {
                const float* base = Ps + ww * PS_CH + b * PS_LD + j;
                s0 += base[0]; s1 += base[8]; s2 += base[16]; s3 += base[24];
            }
            float fg = s0 + bias0 + gx0;
            float ig = s1 + bias1 + gx1;
            float cg = s2 + bias2 + gx2;
            float og = s3 + bias3 + gx3;
            float fs = 1.f / (1.f + __expf(-fg));
            float is = 1.f / (1.f + __expf(-ig));
            float os = 1.f / (1.f + __expf(-og));
            cell = fs * cell + is * tanhf(cg);
            float h = os * tanhf(cell);
            __stcg(hwrite + b * HSZ + cb * JPC + j, h);
            out[((size_t)t * BATCH + b) * HSZ + cb * JPC + j] = h;
        }

        __syncthreads();
        if (tid == 0) red_release_add(g_flags + (cb >> 4), 1u);
    }
}

// ---------------- launch ----------------
extern "C" void kernel_launch(void* const* d_in, const int* in_sizes, int n_in,
                              void* d_out, int out_size)
{
    const float* x  = (const float*)d_in[0];
    const float* Wf = (const float*)d_in[1];
    const float* bf = (const float*)d_in[2];
    const float* Wi = (const float*)d_in[3];
    const float* bi = (const float*)d_in[4];
    const float* Wc = (const float*)d_in[5];
    const float* bc = (const float*)d_in[6];
    const float* Wo = (const float*)d_in[7];
    const float* bo = (const float*)d_in[8];
    float* out = (float*)d_out;

    cudaFuncSetAttribute(gx_kernel, cudaFuncAttributeMaxDynamicSharedMemorySize, GX_SMEM);
    cudaFuncSetAttribute(lstm_seq_kernel, cudaFuncAttributeMaxDynamicSharedMemorySize, SEQ_SMEM);

    reset_kernel<<<1, 32>>>();

    int n_pack = NC * HSZ * RPC + NC * ISZ * RPC + NC * RPC;
    pack_kernel<<<(n_pack + 255) / 256, 256>>>(Wf, Wi, Wc, Wo, bf, bi, bc, bo);

    dim3 ggrid(4096 / 128, (T_LEN * BATCH) / 128);   // (32, 256)
    gx_kernel<<<ggrid, 256, GX_SMEM>>>(x);

    lstm_seq_kernel<<<NC, 512, SEQ_SMEM>>>(out);

    (void)in_sizes; (void)n_in; (void)out_size;
}

// round 11
// speedup vs baseline: 2.0120x; 1.3614x over previous
#include <cuda_runtime.h>
#include <mma.h>
#include <cstdint>
#include <cstdio>

using namespace nvcuda;

#define T_LEN 512
#define BATCH 64
#define ISZ   512
#define HSZ   1024
#define HX    1536
#define NC    128      // c-groups == CTAs in sequential kernel
#define RPC   32       // gate rows per c-group (f8,i8,c8,o8)
#define JPC   8        // h columns per c-group

// ---------------- static device scratch (no cudaMalloc allowed) ----------------
__device__ float    g_Wrec[NC * HSZ * RPC];              // [c][k][r] tf32-rounded, 16 MB
__device__ float    g_Wx[NC * ISZ * RPC];                // [c][k][r] tf32-rounded, 8 MB
__device__ float    g_bg[NC * RPC];                      // packed biases
__device__ float    g_Gx[(size_t)T_LEN * NC * BATCH * RPC]; // [t][c][b][r], 512 MB
__device__ float    g_h[2 * BATCH * HSZ];                // double-buffered hidden state
__device__ unsigned g_flags[8];                          // per-chunk cumulative arrival counters

__global__ void reset_kernel() { if (threadIdx.x < 8) g_flags[threadIdx.x] = 0u; }

// ---------------- pack: transpose weights into per-c k-major blocks ----------------
__global__ void pack_kernel(const float* __restrict__ Wf, const float* __restrict__ Wi,
                            const float* __restrict__ Wc, const float* __restrict__ Wo,
                            const float* __restrict__ bf, const float* __restrict__ bi,
                            const float* __restrict__ bc, const float* __restrict__ bo)
{
    int idx = blockIdx.x * blockDim.x + threadIdx.x;
    const int N1 = NC * HSZ * RPC;   // 4194304
    const int N2 = NC * ISZ * RPC;   // 2097152
    if (idx < N1) {
        int r = idx & 31; int k = (idx >> 5) & 1023; int c = idx >> 15;
        int gate = r >> 3; int j = c * JPC + (r & 7);
        const float* W = (gate == 0) ? Wf : (gate == 1) ? Wi : (gate == 2) ? Wc : Wo;
        g_Wrec[idx] = wmma::__float_to_tf32(W[(size_t)j * HX + k]);
    } else if (idx < N1 + N2) {
        int t2 = idx - N1;
        int r = t2 & 31; int k = (t2 >> 5) & 511; int c = t2 >> 14;
        int gate = r >> 3; int j = c * JPC + (r & 7);
        const float* W = (gate == 0) ? Wf : (gate == 1) ? Wi : (gate == 2) ? Wc : Wo;
        g_Wx[t2] = wmma::__float_to_tf32(W[(size_t)j * HX + HSZ + k]);
    } else if (idx < N1 + N2 + NC * RPC) {
        int t3 = idx - N1 - N2;
        int r = t3 & 31; int c = t3 >> 5;
        int gate = r >> 3; int j = c * JPC + (r & 7);
        const float* b = (gate == 0) ? bf : (gate == 1) ? bi : (gate == 2) ? bc : bo;
        g_bg[t3] = b[j];
    }
}

// ---------------- Gx = x @ Wx^T, written as [t][c][b][r] ----------------
#define GX_LDA 132
#define GX_SMEM (2 * 128 * GX_LDA * 4)

__global__ __launch_bounds__(256, 1) void gx_kernel(const float* __restrict__ x)
{
    extern __shared__ float sm[];
    float* As = sm;                   // 128 x 132
    float* Bs = sm + 128 * GX_LDA;    // 128 x 132
    int tid = threadIdx.x;
    int w = tid >> 5;
    int m0 = blockIdx.y * 128;        // 2 timesteps
    int n0 = blockIdx.x * 128;        // 4 c-groups
    int c0 = n0 >> 5;

    wmma::fragment<wmma::accumulator, 16, 16, 8, float> acc[8];
#pragma unroll
    for (int i = 0; i < 8; i++) wmma::fill_fragment(acc[i], 0.f);

    for (int kb = 0; kb < ISZ; kb += 128) {
#pragma unroll
        for (int it = 0; it < 16; ++it) {
            int p4 = tid + it * 256;
            int row = p4 >> 5, col4 = p4 & 31;
            float4 v = *(const float4*)(x + (size_t)(m0 + row) * ISZ + kb + col4 * 4);
            v.x = wmma::__float_to_tf32(v.x); v.y = wmma::__float_to_tf32(v.y);
            v.z = wmma::__float_to_tf32(v.z); v.w = wmma::__float_to_tf32(v.w);
            *(float4*)(As + row * GX_LDA + col4 * 4) = v;
        }
#pragma unroll
        for (int it = 0; it < 16; ++it) {
            int p4 = tid + it * 256;
            int cl = p4 >> 10; int rem = p4 & 1023;
            int k = rem >> 3; int r4 = rem & 7;
            float4 v = *(const float4*)(g_Wx + ((size_t)(c0 + cl) * ISZ + kb + k) * RPC + r4 * 4);
            *(float4*)(Bs + k * GX_LDA + cl * 32 + r4 * 4) = v;
        }
        __syncthreads();
#pragma unroll 4
        for (int ks = 0; ks < 128; ks += 8) {
            wmma::fragment<wmma::matrix_a, 16, 16, 8, wmma::precision::tf32, wmma::row_major> a;
            wmma::load_matrix_sync(a, As + (w * 16) * GX_LDA + ks, GX_LDA);
#pragma unroll
            for (int nt = 0; nt < 8; ++nt) {
                wmma::fragment<wmma::matrix_b, 16, 16, 8, wmma::precision::tf32, wmma::row_major> b;
                wmma::load_matrix_sync(b, Bs + ks * GX_LDA + nt * 16, GX_LDA);
                wmma::mma_sync(acc[nt], a, b, acc[nt]);
            }
        }
        __syncthreads();
    }
    int mg = m0 + w * 16;
    int t = mg >> 6; int b0 = mg & 63;
#pragma unroll
    for (int nt = 0; nt < 8; ++nt) {
        int ng = n0 + nt * 16;
        int c = ng >> 5; int r0 = ng & 31;
        float* dst = g_Gx + ((size_t)(t * NC + c) * BATCH + b0) * RPC + r0;
        wmma::store_matrix_sync(dst, acc[nt], RPC, wmma::mem_row_major);
    }
}

// ---------------- persistent sequential LSTM kernel ----------------
// 512 threads = 16 warps. Warp (mh = w>>3, kw = w&7) owns M rows [mh*32, mh*32+32)
// and K columns [kw*128, (kw+1)*128). Single-pass tf32 on h (no hi/lo split).
// Warp-private A staging; no block syncs in the MMA loop; acquire/release flags.
#define WS_LD     36                       // Ws leading dim
#define A_LD      20                       // A sub-chunk leading dim (80B rows)
#define AW_STRIDE (32 * A_LD)              // floats per warp = 640
#define PS_LD     36                       // multiple of 4 (wmma float ldm rule)
#define PS_CH     (64 * PS_LD)             // 2304 floats per kw-chunk partial
// A region must also hold Ps (8 * 2304 = 18432 floats > 16*640 = 10240)
#define A_REGION  18432
#define SEQ_SMEM  ((HSZ * WS_LD + A_REGION) * 4)   // 221,184 B

__device__ __forceinline__ unsigned ld_acquire(const unsigned* p)
{
    unsigned v;
    asm volatile("ld.acquire.gpu.global.u32 %0, [%1];" : "=r"(v) : "l"(p) : "memory");
    return v;
}
__device__ __forceinline__ void red_release_add(unsigned* p, unsigned v)
{
    asm volatile("red.release.gpu.global.add.u32 [%0], %1;" :: "l"(p), "r"(v) : "memory");
}

__global__ __launch_bounds__(512, 1) void lstm_seq_kernel(float* __restrict__ out)
{
    extern __shared__ float sm[];
    float* Ws    = sm;                         // [1024][36] Wh slice (tf32, padded)
    float* Abase = sm + HSZ * WS_LD;           // per-warp A buffers; aliased by Ps
    float* Ps    = Abase;                      // [8][64][36] chunk partials (epilogue only)

    int tid  = threadIdx.x;
    int w    = tid >> 5;
    int lane = tid & 31;
    int kw   = w & 7;                  // K-chunk owned
    int mh   = w >> 3;                 // M half owned
    int cb   = blockIdx.x;

    float* AW = Abase + w * AW_STRIDE;         // [32][20] single tf32 A buffer

    // ---- init: Ws copy (padded), per-thread bias/cell regs, zero h_{-1} ----
    {
        const float4* wsrc = (const float4*)(g_Wrec + (size_t)cb * HSZ * RPC);
        for (int i = tid; i < HSZ * RPC / 4; i += 512) {
            int k = i >> 3, r4 = i & 7;
            ((float4*)(Ws + k * WS_LD))[r4] = wsrc[i];
        }
    }
    int b = tid >> 3;                  // batch row owned (8 threads per b)
    int j = tid & 7;                   // h column owned: exactly one (b,j) per thread
    float bias0, bias1, bias2, bias3;
    {
        const float* bg = g_bg + cb * RPC;
        bias0 = bg[j]; bias1 = bg[8 + j]; bias2 = bg[16 + j]; bias3 = bg[24 + j];
    }
    float cell = 0.f;
    __stcg(g_h + b * HSZ + cb * JPC + j, 0.f);   // h_{-1} in buffer 0
    __syncthreads();
    if (tid == 0) red_release_add(&g_flags[cb >> 4], 1u);

    int r0row = lane >> 2;             // staging: row sub-index (0..7)
    int c4    = lane & 3;              // staging: col group (4 floats)
    int mbase = mh * 32;               // this warp's global M offset

    for (int t = 0; t < T_LEN; ++t) {
        const float* hread = g_h + (size_t)(t & 1) * BATCH * HSZ;
        float* hwrite      = g_h + (size_t)((t + 1) & 1) * BATCH * HSZ;

        // prefetch Gx early (independent of flag) to hide DRAM latency
        const float* gxb = g_Gx + ((size_t)(t * NC + cb) * BATCH + b) * RPC;
        float gx0 = __ldcg(gxb + j);
        float gx1 = __ldcg(gxb + 8 + j);
        float gx2 = __ldcg(gxb + 16 + j);
        float gx3 = __ldcg(gxb + 24 + j);

        // per-warp wait: chunk kw of h_{t-1} fully written (16 producer CTAs)
        {
            unsigned tgt = 16u * (unsigned)(t + 1);
            while (ld_acquire(g_flags + kw) < tgt) __nanosleep(32);
        }

        wmma::fragment<wmma::accumulator, 16, 16, 8, float> acc[2][2];
#pragma unroll
        for (int mt = 0; mt < 2; ++mt)
#pragma unroll
            for (int nt = 0; nt < 2; ++nt) wmma::fill_fragment(acc[mt][nt], 0.f);

        const float* hw = hread + kw * 128;

        // prologue: load sub-chunk 0 into registers (4 rows-of-8 per lane group)
        float4 rg[4];
#pragma unroll
        for (int p = 0; p < 4; ++p)
            rg[p] = __ldcg((const float4*)(hw + (size_t)(mbase + p * 8 + r0row) * HSZ + c4 * 4));

        for (int s = 0; s < 8; ++s) {
            // tf32-round h and stage into warp-private buffer (single pass)
#pragma unroll
            for (int p = 0; p < 4; ++p) {
                float4 v = rg[p], hi;
                hi.x = wmma::__float_to_tf32(v.x);
                hi.y = wmma::__float_to_tf32(v.y);
                hi.z = wmma::__float_to_tf32(v.z);
                hi.w = wmma::__float_to_tf32(v.w);
                int row = p * 8 + r0row;
                *(float4*)(AW + row * A_LD + c4 * 4) = hi;
            }
            // register-prefetch next sub-chunk (L2 latency hidden behind MMA below)
            if (s < 7) {
#pragma unroll
                for (int p = 0; p < 4; ++p)
                    rg[p] = __ldcg((const float4*)(hw + (size_t)(mbase + p * 8 + r0row) * HSZ
                                                   + (s + 1) * 16 + c4 * 4));
            }
            __syncwarp();   // STS visible to all lanes before warp-collective loads

            const float* WsW = Ws + (size_t)(kw * 128 + s * 16) * WS_LD;
#pragma unroll
            for (int ks = 0; ks < 2; ++ks) {
                wmma::fragment<wmma::matrix_b, 16, 16, 8, wmma::precision::tf32, wmma::row_major> b0, b1;
                wmma::load_matrix_sync(b0, WsW + ks * 8 * WS_LD, WS_LD);
                wmma::load_matrix_sync(b1, WsW + ks * 8 * WS_LD + 16, WS_LD);
                wmma::fragment<wmma::matrix_a, 16, 16, 8, wmma::precision::tf32, wmma::row_major> a[2];
#pragma unroll
                for (int mt = 0; mt < 2; ++mt)
                    wmma::load_matrix_sync(a[mt], AW + (mt * 16) * A_LD + ks * 8, A_LD);
#pragma unroll
                for (int mt = 0; mt < 2; ++mt) {
                    wmma::mma_sync(acc[mt][0], a[mt], b0, acc[mt][0]);
                    wmma::mma_sync(acc[mt][1], a[mt], b1, acc[mt][1]);
                }
            }
        }

        __syncthreads();   // all warps done with A buffers; Ps region free
#pragma unroll
        for (int mt = 0; mt < 2; ++mt)
#pragma unroll
            for (int nt = 0; nt < 2; ++nt)
                wmma::store_matrix_sync(Ps + kw * PS_CH + (mbase + mt * 16) * PS_LD + nt * 16,
                                        acc[mt][nt], PS_LD, wmma::mem_row_major);
        __syncthreads();

        // reduce 8 chunk-partials + fused activations + cell update + h/out write
        {
            float s0 = 0.f, s1 = 0.f, s2 = 0.f, s3 = 0.f;
#pragma unroll
            for (int ww = 0; ww < 8; ++ww) {
                const float* base = Ps + ww * PS_CH + b * PS_LD + j;
                s0 += base[0]; s1 += base[8]; s2 += base[16]; s3 += base[24];
            }
            float fg = s0 + bias0 + gx0;
            float ig = s1 + bias1 + gx1;
            float cg = s2 + bias2 + gx2;
            float og = s3 + bias3 + gx3;
            float fs = 1.f / (1.f + __expf(-fg));
            float is = 1.f / (1.f + __expf(-ig));
            float os = 1.f / (1.f + __expf(-og));
            cell = fs * cell + is * tanhf(cg);
            float h = os * tanhf(cell);
            __stcg(hwrite + b * HSZ + cb * JPC + j, h);
            out[((size_t)t * BATCH + b) * HSZ + cb * JPC + j] = h;
        }

        __syncthreads();
        if (tid == 0) red_release_add(g_flags + (cb >> 4), 1u);
    }
}

// ---------------- launch ----------------
extern "C" void kernel_launch(void* const* d_in, const int* in_sizes, int n_in,
                              void* d_out, int out_size)
{
    const float* x  = (const float*)d_in[0];
    const float* Wf = (const float*)d_in[1];
    const float* bf = (const float*)d_in[2];
    const float* Wi = (const float*)d_in[3];
    const float* bi = (const float*)d_in[4];
    const float* Wc = (const float*)d_in[5];
    const float* bc = (const float*)d_in[6];
    const float* Wo = (const float*)d_in[7];
    const float* bo = (const float*)d_in[8];
    float* out = (float*)d_out;

    cudaFuncSetAttribute(gx_kernel, cudaFuncAttributeMaxDynamicSharedMemorySize, GX_SMEM);
    cudaFuncSetAttribute(lstm_seq_kernel, cudaFuncAttributeMaxDynamicSharedMemorySize, SEQ_SMEM);

    reset_kernel<<<1, 32>>>();

    int n_pack = NC * HSZ * RPC + NC * ISZ * RPC + NC * RPC;
    pack_kernel<<<(n_pack + 255) / 256, 256>>>(Wf, Wi, Wc, Wo, bf, bi, bc, bo);

    dim3 ggrid(4096 / 128, (T_LEN * BATCH) / 128);   // (32, 256)
    gx_kernel<<<ggrid, 256, GX_SMEM>>>(x);

    lstm_seq_kernel<<<NC, 512, SEQ_SMEM>>>(out);

    (void)in_sizes; (void)n_in; (void)out_size;
}

// round 13
// speedup vs baseline: 2.5020x; 1.2435x over previous
#include <cuda_runtime.h>
#include <mma.h>
#include <cstdint>

using namespace nvcuda;

#define T_LEN 512
#define BATCH 64
#define ISZ   512
#define HSZ   1024
#define HX    1536
#define NC    128      // c-groups == CTAs in sequential kernel
#define RPC   32       // gate rows per c-group (f8,i8,c8,o8)
#define JPC   8        // h columns per c-group

// ---------------- static device scratch (no cudaMalloc allowed) ----------------
__device__ float    g_Wrec[NC * HSZ * RPC];              // [c][k][r] tf32-rounded, 16 MB
__device__ float    g_Wx[NC * ISZ * RPC];                // [c][k][r] tf32-rounded, 8 MB
__device__ float    g_bg[NC * RPC];                      // packed biases
__device__ float    g_Gx[(size_t)T_LEN * NC * BATCH * RPC]; // [t][c][b][r], 512 MB
__device__ float    g_h[2 * BATCH * HSZ];                // double-buffered hidden state
__device__ unsigned g_flags[8];                          // per-chunk cumulative arrival counters

__global__ void reset_kernel() { if (threadIdx.x < 8) g_flags[threadIdx.x] = 0u; }

// ---------------- pack: transpose weights into per-c k-major blocks ----------------
__global__ void pack_kernel(const float* __restrict__ Wf, const float* __restrict__ Wi,
                            const float* __restrict__ Wc, const float* __restrict__ Wo,
                            const float* __restrict__ bf, const float* __restrict__ bi,
                            const float* __restrict__ bc, const float* __restrict__ bo)
{
    int idx = blockIdx.x * blockDim.x + threadIdx.x;
    const int N1 = NC * HSZ * RPC;   // 4194304
    const int N2 = NC * ISZ * RPC;   // 2097152
    if (idx < N1) {
        int r = idx & 31; int k = (idx >> 5) & 1023; int c = idx >> 15;
        int gate = r >> 3; int j = c * JPC + (r & 7);
        const float* W = (gate == 0) ? Wf : (gate == 1) ? Wi : (gate == 2) ? Wc : Wo;
        g_Wrec[idx] = wmma::__float_to_tf32(W[(size_t)j * HX + k]);
    } else if (idx < N1 + N2) {
        int t2 = idx - N1;
        int r = t2 & 31; int k = (t2 >> 5) & 511; int c = t2 >> 14;
        int gate = r >> 3; int j = c * JPC + (r & 7);
        const float* W = (gate == 0) ? Wf : (gate == 1) ? Wi : (gate == 2) ? Wc : Wo;
        g_Wx[t2] = wmma::__float_to_tf32(W[(size_t)j * HX + HSZ + k]);
    } else if (idx < N1 + N2 + NC * RPC) {
        int t3 = idx - N1 - N2;
        int r = t3 & 31; int c = t3 >> 5;
        int gate = r >> 3; int j = c * JPC + (r & 7);
        const float* b = (gate == 0) ? bf : (gate == 1) ? bi : (gate == 2) ? bc : bo;
        g_bg[t3] = b[j];
    }
}

// ---------------- Gx = x @ Wx^T, written as [t][c][b][r] (unchanged) ----------------
#define GX_LDA 132
#define GX_SMEM (2 * 128 * GX_LDA * 4)

__global__ __launch_bounds__(256, 1) void gx_kernel(const float* __restrict__ x)
{
    extern __shared__ float sm[];
    float* As = sm;
    float* Bs = sm + 128 * GX_LDA;
    int tid = threadIdx.x;
    int w = tid >> 5;
    int m0 = blockIdx.y * 128;
    int n0 = blockIdx.x * 128;
    int c0 = n0 >> 5;

    wmma::fragment<wmma::accumulator, 16, 16, 8, float> acc[8];
#pragma unroll
    for (int i = 0; i < 8; i++) wmma::fill_fragment(acc[i], 0.f);

    for (int kb = 0; kb < ISZ; kb += 128) {
#pragma unroll
        for (int it = 0; it < 16; ++it) {
            int p4 = tid + it * 256;
            int row = p4 >> 5, col4 = p4 & 31;
            float4 v = *(const float4*)(x + (size_t)(m0 + row) * ISZ + kb + col4 * 4);
            v.x = wmma::__float_to_tf32(v.x); v.y = wmma::__float_to_tf32(v.y);
            v.z = wmma::__float_to_tf32(v.z); v.w = wmma::__float_to_tf32(v.w);
            *(float4*)(As + row * GX_LDA + col4 * 4) = v;
        }
#pragma unroll
        for (int it = 0; it < 16; ++it) {
            int p4 = tid + it * 256;
            int cl = p4 >> 10; int rem = p4 & 1023;
            int k = rem >> 3; int r4 = rem & 7;
            float4 v = *(const float4*)(g_Wx + ((size_t)(c0 + cl) * ISZ + kb + k) * RPC + r4 * 4);
            *(float4*)(Bs + k * GX_LDA + cl * 32 + r4 * 4) = v;
        }
        __syncthreads();
#pragma unroll 4
        for (int ks = 0; ks < 128; ks += 8) {
            wmma::fragment<wmma::matrix_a, 16, 16, 8, wmma::precision::tf32, wmma::row_major> a;
            wmma::load_matrix_sync(a, As + (w * 16) * GX_LDA + ks, GX_LDA);
#pragma unroll
            for (int nt = 0; nt < 8; ++nt) {
                wmma::fragment<wmma::matrix_b, 16, 16, 8, wmma::precision::tf32, wmma::row_major> b;
                wmma::load_matrix_sync(b, Bs + ks * GX_LDA + nt * 16, GX_LDA);
                wmma::mma_sync(acc[nt], a, b, acc[nt]);
            }
        }
        __syncthreads();
    }
    int mg = m0 + w * 16;
    int t = mg >> 6; int b0 = mg & 63;
#pragma unroll
    for (int nt = 0; nt < 8; ++nt) {
        int ng = n0 + nt * 16;
        int c = ng >> 5; int r0 = ng & 31;
        float* dst = g_Gx + ((size_t)(t * NC + c) * BATCH + b0) * RPC + r0;
        wmma::store_matrix_sync(dst, acc[nt], RPC, wmma::mem_row_major);
    }
}

// ---------------- helpers ----------------
__device__ __forceinline__ unsigned ld_acquire(const unsigned* p) {
    unsigned v;
    asm volatile("ld.acquire.gpu.global.u32 %0, [%1];" : "=r"(v) : "l"(p) : "memory");
    return v;
}
__device__ __forceinline__ void red_release_add(unsigned* p, unsigned v) {
    asm volatile("red.release.gpu.global.add.u32 [%0], %1;" :: "l"(p), "r"(v) : "memory");
}
// mma.sync m16n8k8 tf32: D[16x8] += A[16x8] * B[8x8]
__device__ __forceinline__ void mma_tf32(float* d, uint32_t a0, uint32_t a1,
                                         uint32_t a2, uint32_t a3,
                                         uint32_t b0, uint32_t b1) {
    asm volatile(
        "mma.sync.aligned.m16n8k8.row.col.f32.tf32.tf32.f32 "
        "{%0,%1,%2,%3}, {%4,%5,%6,%7}, {%8,%9}, {%0,%1,%2,%3};"
        : "+f"(d[0]), "+f"(d[1]), "+f"(d[2]), "+f"(d[3])
        : "r"(a0), "r"(a1), "r"(a2), "r"(a3), "r"(b0), "r"(b1));
}

// ---------------- persistent sequential LSTM kernel (manual MMA, B in registers) ----
// 256 threads = 8 warps. Warp w owns K-chunk [w*128, (w+1)*128), computes full
// D[64 batch x 32 gates] partial. B (Ws) fragments persistent in registers.
#define AS_LD   20                      // staged A leading dim (conflict-free for frag LDS)
#define AS_W    (64 * AS_LD)            // 1280 floats per warp
#define PS_LD   36
#define PS_CH   (64 * PS_LD)            // 2304 floats per warp partial
#define BG_OFF  (8 * PS_CH)             // biases after Ps region
#define SEQ_SMEM ((8 * PS_CH + 32) * 4) // 73,856 B (A buffers alias Ps region)

__global__ __launch_bounds__(256, 1) void lstm_seq_kernel(float* __restrict__ out)
{
    extern __shared__ float sm[];
    float* Ps = sm;                    // [8][64][36] partials (epilogue)
    float* Bg = sm + BG_OFF;           // [32] biases

    int tid  = threadIdx.x;
    int w    = tid >> 5;
    int lane = tid & 31;
    int c    = lane & 3;               // threadID_in_group
    int r4   = lane >> 2;              // groupID
    int cb   = blockIdx.x;

    float* As = sm + w * AS_W;         // [64][20] warp-private staged A (aliases Ps)

    // ---- persistent B fragments: 16 kg x 4 nt x 2 regs, loaded once ----
    uint32_t breg[128];
    {
        const float* Wcb = g_Wrec + (size_t)cb * (HSZ * RPC);
#pragma unroll
        for (int kg = 0; kg < 16; ++kg)
#pragma unroll
            for (int nt = 0; nt < 4; ++nt) {
                breg[(kg * 4 + nt) * 2 + 0] =
                    __float_as_uint(Wcb[(size_t)(w * 128 + kg * 8 + c) * RPC + nt * 8 + r4]);
                breg[(kg * 4 + nt) * 2 + 1] =
                    __float_as_uint(Wcb[(size_t)(w * 128 + kg * 8 + 4 + c) * RPC + nt * 8 + r4]);
            }
    }

    if (tid < RPC) Bg[tid] = g_bg[cb * RPC + tid];

    int b  = tid >> 2;                 // batch row owned (4 threads per b)
    int j0 = (2 * tid) & 7;            // this thread owns cells (b,j0),(b,j0+1)
    float cell0 = 0.f, cell1 = 0.f;
    {
        float2 z; z.x = 0.f; z.y = 0.f;
        __stcg((float2*)(g_h + b * HSZ + cb * JPC + j0), z);   // h_{-1} in buffer 0
    }
    __syncthreads();
    if (tid == 0) red_release_add(&g_flags[cb >> 4], 1u);

    for (int t = 0; t < T_LEN; ++t) {
        const float* hread = g_h + (size_t)(t & 1) * BATCH * HSZ;
        float* hwrite      = g_h + (size_t)((t + 1) & 1) * BATCH * HSZ;

        // prefetch Gx early (hides DRAM latency behind the MMA loop)
        float gxr[8];
        {
            const float* gxb = g_Gx + ((size_t)(t * NC + cb) * BATCH + b) * RPC;
            gxr[0] = __ldcg(gxb + j0);      gxr[1] = __ldcg(gxb + 8 + j0);
            gxr[2] = __ldcg(gxb + 16 + j0); gxr[3] = __ldcg(gxb + 24 + j0);
            gxr[4] = __ldcg(gxb + j0 + 1);      gxr[5] = __ldcg(gxb + 8 + j0 + 1);
            gxr[6] = __ldcg(gxb + 16 + j0 + 1); gxr[7] = __ldcg(gxb + 24 + j0 + 1);
        }

        // per-warp wait: chunk w of h_{t-1} fully written (16 producer CTAs)
        {
            unsigned tgt = 16u * (unsigned)(t + 1);
            while (ld_acquire(g_flags + w) < tgt) __nanosleep(32);
        }

        float acc[4][4][4];            // [mt][nt][reg]
#pragma unroll
        for (int mt = 0; mt < 4; ++mt)
#pragma unroll
            for (int nt = 0; nt < 4; ++nt)
#pragma unroll
                for (int q = 0; q < 4; ++q) acc[mt][nt][q] = 0.f;

        const float* hw = hread + w * 128;

#pragma unroll
        for (int s = 0; s < 8; ++s) {
            // stage 64 rows x 16 k (tf32-rounded); fully coalesced LDG.128
#pragma unroll
            for (int i = 0; i < 8; ++i) {
                float4 v = __ldcg((const float4*)(hw + (size_t)(i * 8 + r4) * HSZ + s * 16 + c * 4));
                v.x = wmma::__float_to_tf32(v.x);
                v.y = wmma::__float_to_tf32(v.y);
                v.z = wmma::__float_to_tf32(v.z);
                v.w = wmma::__float_to_tf32(v.w);
                *(float4*)(As + (i * 8 + r4) * AS_LD + c * 4) = v;
            }
            __syncwarp();
#pragma unroll
            for (int kk = 0; kk < 2; ++kk) {
                int kg = s * 2 + kk;
#pragma unroll
                for (int mt = 0; mt < 4; ++mt) {
                    uint32_t a0 = __float_as_uint(As[(mt * 16 + r4) * AS_LD + kk * 8 + c]);
                    uint32_t a1 = __float_as_uint(As[(mt * 16 + 8 + r4) * AS_LD + kk * 8 + c]);
                    uint32_t a2 = __float_as_uint(As[(mt * 16 + r4) * AS_LD + kk * 8 + 4 + c]);
                    uint32_t a3 = __float_as_uint(As[(mt * 16 + 8 + r4) * AS_LD + kk * 8 + 4 + c]);
#pragma unroll
                    for (int nt = 0; nt < 4; ++nt)
                        mma_tf32(acc[mt][nt], a0, a1, a2, a3,
                                 breg[(kg * 4 + nt) * 2], breg[(kg * 4 + nt) * 2 + 1]);
                }
            }
            __syncwarp();   // all lanes done reading As before next stage overwrites
        }

        __syncthreads();   // all warps done with As; Ps region free
        // store partials: c0,c1 = row(groupID), cols 2c,2c+1; c2,c3 = row+8
#pragma unroll
        for (int mt = 0; mt < 4; ++mt)
#pragma unroll
            for (int nt = 0; nt < 4; ++nt) {
                float2 lo, hi2;
                lo.x  = acc[mt][nt][0]; lo.y  = acc[mt][nt][1];
                hi2.x = acc[mt][nt][2]; hi2.y = acc[mt][nt][3];
                *(float2*)(Ps + w * PS_CH + (mt * 16 + r4) * PS_LD + nt * 8 + 2 * c) = lo;
                *(float2*)(Ps + w * PS_CH + (mt * 16 + 8 + r4) * PS_LD + nt * 8 + 2 * c) = hi2;
            }
        __syncthreads();

        // reduce 8 warp-partials + fused activations + cell update + h/out write
        {
            float s0 = 0.f, s1 = 0.f, s2 = 0.f, s3 = 0.f;
            float u0 = 0.f, u1 = 0.f, u2 = 0.f, u3 = 0.f;
#pragma unroll
            for (int ww = 0; ww < 8; ++ww) {
                const float* base = Ps + ww * PS_CH + b * PS_LD + j0;
                s0 += base[0];  s1 += base[8];  s2 += base[16]; s3 += base[24];
                u0 += base[1];  u1 += base[9];  u2 += base[17]; u3 += base[25];
            }
            float fg0 = s0 + Bg[j0]      + gxr[0], fg1 = u0 + Bg[j0 + 1]      + gxr[4];
            float ig0 = s1 + Bg[8 + j0]  + gxr[1], ig1 = u1 + Bg[8 + j0 + 1]  + gxr[5];
            float cg0 = s2 + Bg[16 + j0] + gxr[2], cg1 = u2 + Bg[16 + j0 + 1] + gxr[6];
            float og0 = s3 + Bg[24 + j0] + gxr[3], og1 = u3 + Bg[24 + j0 + 1] + gxr[7];
            float fs0 = 1.f / (1.f + __expf(-fg0)), fs1 = 1.f / (1.f + __expf(-fg1));
            float is0 = 1.f / (1.f + __expf(-ig0)), is1 = 1.f / (1.f + __expf(-ig1));
            float os0 = 1.f / (1.f + __expf(-og0)), os1 = 1.f / (1.f + __expf(-og1));
            cell0 = fs0 * cell0 + is0 * tanhf(cg0);
            cell1 = fs1 * cell1 + is1 * tanhf(cg1);
            float2 hv;
            hv.x = os0 * tanhf(cell0);
            hv.y = os1 * tanhf(cell1);
            __stcg((float2*)(hwrite + b * HSZ + cb * JPC + j0), hv);
            *(float2*)(out + ((size_t)t * BATCH + b) * HSZ + cb * JPC + j0) = hv;
        }

        __syncthreads();
        if (tid == 0) red_release_add(g_flags + (cb >> 4), 1u);
    }
}

// ---------------- launch ----------------
extern "C" void kernel_launch(void* const* d_in, const int* in_sizes, int n_in,
                              void* d_out, int out_size)
{
    const float* x  = (const float*)d_in[0];
    const float* Wf = (const float*)d_in[1];
    const float* bf = (const float*)d_in[2];
    const float* Wi = (const float*)d_in[3];
    const float* bi = (const float*)d_in[4];
    const float* Wc = (const float*)d_in[5];
    const float* bc = (const float*)d_in[6];
    const float* Wo = (const float*)d_in[7];
    const float* bo = (const float*)d_in[8];
    float* out = (float*)d_out;

    cudaFuncSetAttribute(gx_kernel, cudaFuncAttributeMaxDynamicSharedMemorySize, GX_SMEM);
    cudaFuncSetAttribute(lstm_seq_kernel, cudaFuncAttributeMaxDynamicSharedMemorySize, SEQ_SMEM);

    reset_kernel<<<1, 32>>>();

    int n_pack = NC * HSZ * RPC + NC * ISZ * RPC + NC * RPC;
    pack_kernel<<<(n_pack + 255) / 256, 256>>>(Wf, Wi, Wc, Wo, bf, bi, bc, bo);

    dim3 ggrid(4096 / 128, (T_LEN * BATCH) / 128);   // (32, 256)
    gx_kernel<<<ggrid, 256, GX_SMEM>>>(x);

    lstm_seq_kernel<<<NC, 256, SEQ_SMEM>>>(out);

    (void)in_sizes; (void)n_in; (void)out_size;
}